// round 15
// baseline (speedup 1.0000x reference)
#include <cuda_runtime.h>
#include <cuda_bf16.h>
#include <cstdint>

#define S_LEN 1728
#define B_SZ 2
#define E_DIM 256
#define H_NUM 8
#define P_DIM 32
#define M_ROWS (B_SZ * S_LEN)   // 3456

#define QT 64                   // q rows per block (attn): 27 tiles exactly
#define ATW 4                   // attn warps per block
#define ATT (ATW * 32)          // 128 threads
#define KN 64                   // keys per tile (attn)
#define NKT (S_LEN / KN)        // 27

#define LOG2E 1.44269504088896340736f

// GEMM smem ring geometry (elements)
#define GA_ELE (128 * 40)
#define GB_ELE (64 * 40)
#define GBUF_ELE (2 * GA_ELE + 2 * GB_ELE)          // Ah,Al,Bh,Bl
#define GEMM_SMEM_BYTES (3 * GBUF_ELE * 2)          // 3-stage ring, bf16

// split-bf16 scratch (no allocations allowed)
__device__ __align__(16) __nv_bfloat16 g_qh[B_SZ * H_NUM * S_LEN * P_DIM]; // [B,H,S,P]
__device__ __align__(16) __nv_bfloat16 g_ql[B_SZ * H_NUM * S_LEN * P_DIM];
__device__ __align__(16) __nv_bfloat16 g_kh[B_SZ * H_NUM * S_LEN * P_DIM];
__device__ __align__(16) __nv_bfloat16 g_kl[B_SZ * H_NUM * S_LEN * P_DIM];
__device__ __align__(16) __nv_bfloat16 g_vth[B_SZ * H_NUM * P_DIM * S_LEN]; // [B,H,P,S]
__device__ __align__(16) __nv_bfloat16 g_vtl[B_SZ * H_NUM * P_DIM * S_LEN];
__device__ __align__(16) __nv_bfloat16 g_xh[M_ROWS * E_DIM];
__device__ __align__(16) __nv_bfloat16 g_xl[M_ROWS * E_DIM];
__device__ __align__(16) __nv_bfloat16 g_wth[4 * E_DIM * E_DIM];  // Wt[n][k], z=q,k,v,o
__device__ __align__(16) __nv_bfloat16 g_wtl[4 * E_DIM * E_DIM];
__device__ __align__(16) __nv_bfloat16 g_oh[M_ROWS * E_DIM];      // attn out hi
__device__ __align__(16) __nv_bfloat16 g_ol[M_ROWS * E_DIM];      // attn out lo

// ---------------------------------------------------------------------------
// helpers
// ---------------------------------------------------------------------------
__device__ __forceinline__ void mma16816(float c[4],
    uint32_t a0, uint32_t a1, uint32_t a2, uint32_t a3,
    uint32_t b0, uint32_t b1)
{
    asm volatile(
        "mma.sync.aligned.m16n8k16.row.col.f32.bf16.bf16.f32 "
        "{%0,%1,%2,%3}, {%4,%5,%6,%7}, {%8,%9}, {%0,%1,%2,%3};"
        : "+f"(c[0]), "+f"(c[1]), "+f"(c[2]), "+f"(c[3])
        : "r"(a0), "r"(a1), "r"(a2), "r"(a3), "r"(b0), "r"(b1));
}

__device__ __forceinline__ void ldsm_x4(uint32_t r[4], uint32_t addr) {
    asm volatile("ldmatrix.sync.aligned.m8n8.x4.shared.b16 {%0,%1,%2,%3}, [%4];"
                 : "=r"(r[0]), "=r"(r[1]), "=r"(r[2]), "=r"(r[3]) : "r"(addr));
}
__device__ __forceinline__ void ldsm_x2(uint32_t r[2], uint32_t addr) {
    asm volatile("ldmatrix.sync.aligned.m8n8.x2.shared.b16 {%0,%1}, [%2];"
                 : "=r"(r[0]), "=r"(r[1]) : "r"(addr));
}

__device__ __forceinline__ uint32_t smem_u32(const void* p) {
    uint32_t a;
    asm("{ .reg .u64 t; cvta.to.shared.u64 t, %1; cvt.u32.u64 %0, t; }"
        : "=r"(a) : "l"(p));
    return a;
}
__device__ __forceinline__ void cp16(uint32_t saddr, const void* g) {
    asm volatile("cp.async.cg.shared.global [%0], [%1], 16;"
                 :: "r"(saddr), "l"(g) : "memory");
}
#define CP_COMMIT() asm volatile("cp.async.commit_group;" ::: "memory")
#define CP_WAIT(N)  asm volatile("cp.async.wait_group %0;" :: "n"(N) : "memory")

__device__ __forceinline__ float ex2f(float x) {
    float y;
    asm("ex2.approx.ftz.f32 %0, %1;" : "=f"(y) : "f"(x));
    return y;
}
// pack (lo, hi) floats into bf16x2 register
__device__ __forceinline__ uint32_t pack_bf16x2(float lo, float hi) {
    uint32_t r;
    asm("cvt.rn.bf16x2.f32 %0, %1, %2;" : "=r"(r) : "f"(hi), "f"(lo));
    return r;
}
__device__ __forceinline__ void split2(float v, __nv_bfloat16& h, __nv_bfloat16& l) {
    h = __float2bfloat16(v);
    l = __float2bfloat16(v - __bfloat162float(h));
}

// ---------------------------------------------------------------------------
// Prep (merged): blocks [0,864) split x; blocks [864,1120) transpose+split W.
// ---------------------------------------------------------------------------
__global__ __launch_bounds__(256) void prep_kernel(
    const float* __restrict__ x,
    const float* __restrict__ Wq, const float* __restrict__ Wk,
    const float* __restrict__ Wv, const float* __restrict__ Wo)
{
    if (blockIdx.x < 864) {
        int i = (blockIdx.x * 256 + threadIdx.x) * 4;
        float4 v = *(const float4*)&x[i];
        uint2 hi, lo;
        hi.x = pack_bf16x2(v.x, v.y);
        hi.y = pack_bf16x2(v.z, v.w);
        lo.x = pack_bf16x2(v.x - __uint_as_float(hi.x << 16),
                           v.y - __uint_as_float(hi.x & 0xffff0000u));
        lo.y = pack_bf16x2(v.z - __uint_as_float(hi.y << 16),
                           v.w - __uint_as_float(hi.y & 0xffff0000u));
        *(uint2*)&g_xh[i] = hi;
        *(uint2*)&g_xl[i] = lo;
    } else {
        __shared__ float s[32][33];
        int bid = blockIdx.x - 864;
        int z = bid >> 6, rem = bid & 63;
        int k0 = (rem & 7) * 32, n0 = (rem >> 3) * 32;
        const float* W = (z == 0) ? Wq : (z == 1) ? Wk : (z == 2) ? Wv : Wo;
        const int c = threadIdx.x & 31, r0 = threadIdx.x >> 5;
        #pragma unroll
        for (int i = 0; i < 4; i++) {
            int r = r0 + i * 8;
            s[r][c] = W[(k0 + r) * E_DIM + n0 + c];
        }
        __syncthreads();
        #pragma unroll
        for (int i = 0; i < 4; i++) {
            int r = r0 + i * 8;
            float v = s[c][r];
            __nv_bfloat16 h, l; split2(v, h, l);
            size_t idx = (size_t)z * E_DIM * E_DIM + (size_t)(n0 + r) * E_DIM + k0 + c;
            g_wth[idx] = h;
            g_wtl[idx] = l;
        }
    }
}

// ---------------------------------------------------------------------------
// Shared GEMM body: C[128,64] = A[128,256] @ Wt[64,256]^T, bf16-split 3-MMA,
// cp.async 3-stage ring + ldmatrix fragments. 256 threads (8 warps 4x2).
// ---------------------------------------------------------------------------
struct GemmFrag {
    float c[2][4][4];
};

__device__ __forceinline__ void gemm_body(
    const __nv_bfloat16* __restrict__ Agh, const __nv_bfloat16* __restrict__ Agl,
    const __nv_bfloat16* __restrict__ wth, const __nv_bfloat16* __restrict__ wtl,
    int m0, int n0, GemmFrag& F)
{
    extern __shared__ __align__(16) char smem_raw[];
    __nv_bfloat16* S = (__nv_bfloat16*)smem_raw;

    const int tid = threadIdx.x;
    const int warp = tid >> 5, lane = tid & 31;
    const int wm = warp >> 1, wn = warp & 1;

    const int ar = tid >> 2, ac = (tid & 3) * 8;
    const int br = tid >> 2, bc = (tid & 3) * 8;

    const int aoffA = (wm * 32 + (lane & 7) + ((lane >> 3) & 1) * 8) * 40 + (lane >> 4) * 8;
    const int aoffB = (wn * 32 + (lane & 7)) * 40 + (lane >> 3) * 8;

    #define GLOAD(kk, b) do {                                                  \
        int _k0 = (kk) * 32;                                                   \
        __nv_bfloat16* Ah_ = S + (b) * GBUF_ELE;                               \
        __nv_bfloat16* Al_ = Ah_ + GA_ELE;                                     \
        __nv_bfloat16* Bh_ = Al_ + GA_ELE;                                     \
        __nv_bfloat16* Bl_ = Bh_ + GB_ELE;                                     \
        cp16(smem_u32(Ah_ + ar * 40 + ac),                                     \
             &Agh[(size_t)(m0 + ar) * E_DIM + _k0 + ac]);                      \
        cp16(smem_u32(Ah_ + (ar + 64) * 40 + ac),                              \
             &Agh[(size_t)(m0 + ar + 64) * E_DIM + _k0 + ac]);                 \
        cp16(smem_u32(Al_ + ar * 40 + ac),                                     \
             &Agl[(size_t)(m0 + ar) * E_DIM + _k0 + ac]);                      \
        cp16(smem_u32(Al_ + (ar + 64) * 40 + ac),                              \
             &Agl[(size_t)(m0 + ar + 64) * E_DIM + _k0 + ac]);                 \
        cp16(smem_u32(Bh_ + br * 40 + bc),                                     \
             &wth[(size_t)(n0 + br) * E_DIM + _k0 + bc]);                      \
        cp16(smem_u32(Bl_ + br * 40 + bc),                                     \
             &wtl[(size_t)(n0 + br) * E_DIM + _k0 + bc]);                      \
    } while (0)

    GLOAD(0, 0); CP_COMMIT();
    GLOAD(1, 1); CP_COMMIT();

    #pragma unroll
    for (int mf = 0; mf < 2; mf++)
        #pragma unroll
        for (int nf = 0; nf < 4; nf++)
            #pragma unroll
            for (int i = 0; i < 4; i++)
                F.c[mf][nf][i] = 0.f;

    for (int kk = 0; kk < 8; kk++) {
        const int b = kk % 3;
        CP_WAIT(1);
        __syncthreads();
        if (kk + 2 < 8) { GLOAD(kk + 2, (kk + 2) % 3); CP_COMMIT(); }
        else { CP_COMMIT(); }

        __nv_bfloat16* Ah_ = S + b * GBUF_ELE;
        __nv_bfloat16* Al_ = Ah_ + GA_ELE;
        __nv_bfloat16* Bh_ = Al_ + GA_ELE;
        __nv_bfloat16* Bl_ = Bh_ + GB_ELE;
        const uint32_t aA_h = smem_u32(Ah_ + aoffA);
        const uint32_t aA_l = smem_u32(Al_ + aoffA);
        const uint32_t aB_h = smem_u32(Bh_ + aoffB);
        const uint32_t aB_l = smem_u32(Bl_ + aoffB);

        uint32_t ah[2][2][4], al[2][2][4];
        #pragma unroll
        for (int mf = 0; mf < 2; mf++) {
            #pragma unroll
            for (int ks = 0; ks < 2; ks++) {
                ldsm_x4(ah[mf][ks], aA_h + mf * (16 * 80) + ks * 32);
                ldsm_x4(al[mf][ks], aA_l + mf * (16 * 80) + ks * 32);
            }
        }
        #pragma unroll
        for (int nf = 0; nf < 4; nf++) {
            uint32_t bh4[4], bl4[4];
            ldsm_x4(bh4, aB_h + nf * (8 * 80));
            ldsm_x4(bl4, aB_l + nf * (8 * 80));
            #pragma unroll
            for (int mf = 0; mf < 2; mf++) {
                #pragma unroll
                for (int ks = 0; ks < 2; ks++) {
                    uint32_t b0h = bh4[2 * ks], b1h = bh4[2 * ks + 1];
                    uint32_t b0l = bl4[2 * ks], b1l = bl4[2 * ks + 1];
                    mma16816(F.c[mf][nf], ah[mf][ks][0], ah[mf][ks][1],
                             ah[mf][ks][2], ah[mf][ks][3], b0h, b1h);
                    mma16816(F.c[mf][nf], al[mf][ks][0], al[mf][ks][1],
                             al[mf][ks][2], al[mf][ks][3], b0h, b1h);
                    mma16816(F.c[mf][nf], ah[mf][ks][0], ah[mf][ks][1],
                             ah[mf][ks][2], ah[mf][ks][3], b0l, b1l);
                }
            }
        }
    }
    CP_WAIT(0);
    #undef GLOAD
}

// ---------------------------------------------------------------------------
// Kernel 1: QKV projection. grid (27, 4, 3), block 256, dynamic smem ring.
// ---------------------------------------------------------------------------
__global__ __launch_bounds__(256) void qkv_mma_kernel(
    const float* __restrict__ bq, const float* __restrict__ bk,
    const float* __restrict__ bv)
{
    const int tid = threadIdx.x;
    const int warp = tid >> 5, lane = tid & 31;
    const int g = lane >> 2, tig = lane & 3;
    const int wm = warp >> 1, wn = warp & 1;
    const int m0 = blockIdx.x * 128;
    const int n0 = blockIdx.y * 64;
    const int z  = blockIdx.z;

    const __nv_bfloat16* wth = g_wth + (size_t)z * E_DIM * E_DIM;
    const __nv_bfloat16* wtl = g_wtl + (size_t)z * E_DIM * E_DIM;
    const float* bias = (z == 0) ? bq : (z == 1) ? bk : bv;
    const float outscale = (z == 0) ? LOG2E : 1.0f;

    GemmFrag F;
    gemm_body(g_xh, g_xl, wth, wtl, m0, n0, F);

    #pragma unroll
    for (int mf = 0; mf < 2; mf++) {
        int rr[2] = { m0 + wm * 32 + mf * 16 + g, m0 + wm * 32 + mf * 16 + g + 8 };
        #pragma unroll
        for (int nf = 0; nf < 4; nf++) {
            int n = n0 + wn * 32 + nf * 8 + 2 * tig;
            int h = n >> 5, p = n & 31;
            float b0 = bias[n], b1 = bias[n + 1];
            #pragma unroll
            for (int half = 0; half < 2; half++) {
                int m = rr[half];
                int bb = m / S_LEN, s = m % S_LEN;
                float v0 = (F.c[mf][nf][2 * half] + b0) * outscale;
                float v1 = (F.c[mf][nf][2 * half + 1] + b1) * outscale;
                __nv_bfloat16 h0, l0, h1, l1;
                split2(v0, h0, l0); split2(v1, h1, l1);
                if (z == 2) {
                    size_t tb = ((size_t)(bb * H_NUM + h) * P_DIM + p) * S_LEN + s;
                    g_vth[tb] = h0; g_vth[tb + S_LEN] = h1;
                    g_vtl[tb] = l0; g_vtl[tb + S_LEN] = l1;
                } else {
                    size_t idx = ((size_t)(bb * H_NUM + h) * S_LEN + s) * P_DIM + p;
                    uint32_t ph = ((uint32_t)__bfloat16_as_ushort(h1) << 16) |
                                  __bfloat16_as_ushort(h0);
                    uint32_t pl = ((uint32_t)__bfloat16_as_ushort(l1) << 16) |
                                  __bfloat16_as_ushort(l0);
                    if (z == 0) { *(uint32_t*)&g_qh[idx] = ph; *(uint32_t*)&g_ql[idx] = pl; }
                    else        { *(uint32_t*)&g_kh[idx] = ph; *(uint32_t*)&g_kl[idx] = pl; }
                }
            }
        }
    }
}

// ---------------------------------------------------------------------------
// Kernel 3: output projection. grid (27, 4), block 256, dynamic smem ring.
// ---------------------------------------------------------------------------
__global__ __launch_bounds__(256) void out_mma_kernel(
    const float* __restrict__ bo, float* __restrict__ out)
{
    const int tid = threadIdx.x;
    const int warp = tid >> 5, lane = tid & 31;
    const int g = lane >> 2, tig = lane & 3;
    const int wm = warp >> 1, wn = warp & 1;
    const int m0 = blockIdx.x * 128;
    const int n0 = blockIdx.y * 64;

    const __nv_bfloat16* wth = g_wth + (size_t)3 * E_DIM * E_DIM;
    const __nv_bfloat16* wtl = g_wtl + (size_t)3 * E_DIM * E_DIM;

    GemmFrag F;
    gemm_body(g_oh, g_ol, wth, wtl, m0, n0, F);

    #pragma unroll
    for (int mf = 0; mf < 2; mf++) {
        int r0 = m0 + wm * 32 + mf * 16 + g;
        int r1 = r0 + 8;
        #pragma unroll
        for (int nf = 0; nf < 4; nf++) {
            int n = n0 + wn * 32 + nf * 8 + 2 * tig;
            float b0 = bo[n], b1 = bo[n + 1];
            *(float2*)&out[(size_t)r0 * E_DIM + n] =
                make_float2(F.c[mf][nf][0] + b0, F.c[mf][nf][1] + b1);
            *(float2*)&out[(size_t)r1 * E_DIM + n] =
                make_float2(F.c[mf][nf][2] + b0, F.c[mf][nf][3] + b1);
        }
    }
}

// ---------------------------------------------------------------------------
// Kernel 2: flash attention; scores and PV interleaved per k-step for ILP.
// grid = (27, 16), block = 128 (4 warps, warp = 16 q rows, QT = 64).
// 432 CTAs = 3 per SM on 144 SMs (balanced wave, small barrier groups).
// ---------------------------------------------------------------------------
__global__ __launch_bounds__(ATT, 3) void attn_mma_kernel()
{
    __shared__ __nv_bfloat16 Kh[2][KN][40], Kl[2][KN][40];
    __shared__ __nv_bfloat16 Vth[2][P_DIM][72], Vtl[2][P_DIM][72];

    const int tid  = threadIdx.x;
    const int warp = tid >> 5, lane = tid & 31;
    const int g    = lane >> 2, tig = lane & 3;
    const int l8   = lane & 7, lq = lane >> 3;
    const int woff = warp * 16;
    const int bh   = blockIdx.y;
    const int q0   = blockIdx.x * QT;

    const size_t bhSP = (size_t)bh * S_LEN * P_DIM;
    const size_t bhPS = (size_t)bh * P_DIM * S_LEN;

    uint32_t aKh[2], aKl[2], aVh[2], aVl[2];
    #pragma unroll
    for (int b = 0; b < 2; b++) {
        aKh[b] = smem_u32(&Kh[b][l8][8 * lq]);
        aKl[b] = smem_u32(&Kl[b][l8][8 * lq]);
        aVh[b] = smem_u32(&Vth[b][l8][8 * lq]);
        aVl[b] = smem_u32(&Vtl[b][l8][8 * lq]);
    }

    #define LOAD_TILE(kt, b) do {                                               \
        int _k0 = (kt) * KN;                                                    \
        for (int i = tid; i < KN * 4; i += ATT) {                               \
            int r = i >> 2, c = (i & 3) * 8;                                    \
            cp16(smem_u32(&Kh[b][r][c]),                                        \
                 &g_kh[bhSP + (size_t)(_k0 + r) * P_DIM + c]);                  \
            cp16(smem_u32(&Kl[b][r][c]),                                        \
                 &g_kl[bhSP + (size_t)(_k0 + r) * P_DIM + c]);                  \
        }                                                                       \
        for (int i = tid; i < P_DIM * 8; i += ATT) {                            \
            int p = i >> 3, c = (i & 7) * 8;                                    \
            cp16(smem_u32(&Vth[b][p][c]),                                       \
                 &g_vth[bhPS + (size_t)p * S_LEN + _k0 + c]);                   \
            cp16(smem_u32(&Vtl[b][p][c]),                                       \
                 &g_vtl[bhPS + (size_t)p * S_LEN + _k0 + c]);                   \
        }                                                                       \
    } while (0)

    LOAD_TILE(0, 0);
    CP_COMMIT();

    const int r0g = q0 + woff + g;
    const size_t qb0 = bhSP + (size_t)r0g * P_DIM;
    const size_t qb1 = qb0 + 8 * P_DIM;
    uint32_t qh[2][4], ql[2][4];
    #pragma unroll
    for (int ks = 0; ks < 2; ks++) {
        int p0 = ks * 16 + 2 * tig;
        qh[ks][0] = *(const uint32_t*)&g_qh[qb0 + p0];
        qh[ks][1] = *(const uint32_t*)&g_qh[qb1 + p0];
        qh[ks][2] = *(const uint32_t*)&g_qh[qb0 + p0 + 8];
        qh[ks][3] = *(const uint32_t*)&g_qh[qb1 + p0 + 8];
        ql[ks][0] = *(const uint32_t*)&g_ql[qb0 + p0];
        ql[ks][1] = *(const uint32_t*)&g_ql[qb1 + p0];
        ql[ks][2] = *(const uint32_t*)&g_ql[qb0 + p0 + 8];
        ql[ks][3] = *(const uint32_t*)&g_ql[qb1 + p0 + 8];
    }

    float o[4][4] = {};
    float l0 = 0.f, l1 = 0.f;

    for (int kt = 0; kt < NKT; kt++) {
        const int buf = kt & 1;
        if (kt + 1 < NKT) {
            LOAD_TILE(kt + 1, buf ^ 1);
            CP_COMMIT();
            CP_WAIT(1);
        } else {
            CP_WAIT(0);
        }
        __syncthreads();

        // interleaved: per k-step, compute 2 score n-tiles then the PV step
        #pragma unroll
        for (int ks = 0; ks < 4; ks++) {
            uint32_t PH01[2], PH23[2], PL01[2], PL23[2];
            #pragma unroll
            for (int t = 0; t < 2; t++) {
                const int nt = 2 * ks + t;
                uint32_t kh4[4], kl4[4];
                ldsm_x4(kh4, aKh[buf] + nt * (8 * 40 * 2));
                ldsm_x4(kl4, aKl[buf] + nt * (8 * 40 * 2));
                float c[4] = {0.f, 0.f, 0.f, 0.f};
                mma16816(c, qh[0][0], qh[0][1], qh[0][2], qh[0][3], kh4[0], kh4[1]);
                mma16816(c, ql[0][0], ql[0][1], ql[0][2], ql[0][3], kh4[0], kh4[1]);
                mma16816(c, qh[0][0], qh[0][1], qh[0][2], qh[0][3], kl4[0], kl4[1]);
                mma16816(c, qh[1][0], qh[1][1], qh[1][2], qh[1][3], kh4[2], kh4[3]);
                mma16816(c, ql[1][0], ql[1][1], ql[1][2], ql[1][3], kh4[2], kh4[3]);
                mma16816(c, qh[1][0], qh[1][1], qh[1][2], qh[1][3], kl4[2], kl4[3]);

                float e0 = ex2f(c[0]);
                float e1 = ex2f(c[1]);
                float e2 = ex2f(c[2]);
                float e3 = ex2f(c[3]);
                l0 += e0 + e1;
                l1 += e2 + e3;
                uint32_t ph01 = pack_bf16x2(e0, e1);
                uint32_t ph23 = pack_bf16x2(e2, e3);
                PH01[t] = ph01;
                PH23[t] = ph23;
                PL01[t] = pack_bf16x2(e0 - __uint_as_float(ph01 << 16),
                                      e1 - __uint_as_float(ph01 & 0xffff0000u));
                PL23[t] = pack_bf16x2(e2 - __uint_as_float(ph23 << 16),
                                      e3 - __uint_as_float(ph23 & 0xffff0000u));
            }
            #pragma unroll
            for (int n = 0; n < 4; n++) {
                uint32_t vh2[2], vl2[2];
                uint32_t base = n * (8 * 72 * 2) + ks * 32;
                ldsm_x2(vh2, aVh[buf] + base);
                ldsm_x2(vl2, aVl[buf] + base);
                mma16816(o[n], PH01[0], PH23[0], PH01[1], PH23[1], vh2[0], vh2[1]);
                mma16816(o[n], PH01[0], PH23[0], PH01[1], PH23[1], vl2[0], vl2[1]);
                mma16816(o[n], PL01[0], PL23[0], PL01[1], PL23[1], vh2[0], vh2[1]);
            }
        }
        __syncthreads();
    }

    l0 += __shfl_xor_sync(0xffffffffu, l0, 1);
    l0 += __shfl_xor_sync(0xffffffffu, l0, 2);
    l1 += __shfl_xor_sync(0xffffffffu, l1, 1);
    l1 += __shfl_xor_sync(0xffffffffu, l1, 2);
    const float inv0 = 1.0f / l0;
    const float inv1 = 1.0f / l1;

    const int b = bh >> 3, h = bh & 7;
    const int r1g = r0g + 8;
    #pragma unroll
    for (int n = 0; n < 4; n++) {
        int p = 8 * n + 2 * tig;
        {
            float w0 = o[n][0] * inv0, w1 = o[n][1] * inv0;
            size_t idx = ((size_t)b * S_LEN + r0g) * E_DIM + h * P_DIM + p;
            uint32_t ph = pack_bf16x2(w0, w1);
            *(uint32_t*)&g_oh[idx] = ph;
            *(uint32_t*)&g_ol[idx] = pack_bf16x2(w0 - __uint_as_float(ph << 16),
                                                 w1 - __uint_as_float(ph & 0xffff0000u));
        }
        {
            float w0 = o[n][2] * inv1, w1 = o[n][3] * inv1;
            size_t idx = ((size_t)b * S_LEN + r1g) * E_DIM + h * P_DIM + p;
            uint32_t ph = pack_bf16x2(w0, w1);
            *(uint32_t*)&g_oh[idx] = ph;
            *(uint32_t*)&g_ol[idx] = pack_bf16x2(w0 - __uint_as_float(ph << 16),
                                                 w1 - __uint_as_float(ph & 0xffff0000u));
        }
    }
}

extern "C" void kernel_launch(void* const* d_in, const int* in_sizes, int n_in,
                              void* d_out, int out_size)
{
    const float* x  = (const float*)d_in[0];
    const float* bq = (const float*)d_in[2];
    const float* bk = (const float*)d_in[4];
    const float* bv = (const float*)d_in[6];
    const float* bo = (const float*)d_in[8];
    float* out = (float*)d_out;

    static bool attr_set = false;
    if (!attr_set) {
        cudaFuncSetAttribute(qkv_mma_kernel,
            cudaFuncAttributeMaxDynamicSharedMemorySize, GEMM_SMEM_BYTES);
        cudaFuncSetAttribute(out_mma_kernel,
            cudaFuncAttributeMaxDynamicSharedMemorySize, GEMM_SMEM_BYTES);
        attr_set = true;
    }

    prep_kernel<<<1120, 256>>>(x,
        (const float*)d_in[1], (const float*)d_in[3],
        (const float*)d_in[5], (const float*)d_in[7]);
    qkv_mma_kernel<<<dim3(27, 4, 3), 256, GEMM_SMEM_BYTES>>>(bq, bk, bv);
    attn_mma_kernel<<<dim3(27, 16), ATT>>>();
    out_mma_kernel<<<dim3(27, 4), 256, GEMM_SMEM_BYTES>>>(bo, out);
}

// round 16
// speedup vs baseline: 1.4153x; 1.4153x over previous
#include <cuda_runtime.h>
#include <cuda_bf16.h>
#include <cstdint>

#define S_LEN 1728
#define B_SZ 2
#define E_DIM 256
#define H_NUM 8
#define P_DIM 32
#define M_ROWS (B_SZ * S_LEN)   // 3456

#define QT 96                   // q rows per block (attn): 18 tiles exactly
#define ATW 6                   // attn warps per block
#define ATT (ATW * 32)          // 192 threads
#define KN 64                   // keys per tile (attn)
#define NKT (S_LEN / KN)        // 27

#define LOG2E 1.44269504088896340736f

// GEMM smem ring geometry (elements)
#define GA_ELE (128 * 40)
#define GB_ELE (64 * 40)
#define GBUF_ELE (2 * GA_ELE + 2 * GB_ELE)          // Ah,Al,Bh,Bl
#define GEMM_SMEM_BYTES (3 * GBUF_ELE * 2)          // 3-stage ring, bf16

// split-bf16 scratch (no allocations allowed)
__device__ __align__(16) __nv_bfloat16 g_qh[B_SZ * H_NUM * S_LEN * P_DIM]; // [B,H,S,P]
__device__ __align__(16) __nv_bfloat16 g_ql[B_SZ * H_NUM * S_LEN * P_DIM];
__device__ __align__(16) __nv_bfloat16 g_kh[B_SZ * H_NUM * S_LEN * P_DIM];
__device__ __align__(16) __nv_bfloat16 g_kl[B_SZ * H_NUM * S_LEN * P_DIM];
__device__ __align__(16) __nv_bfloat16 g_vth[B_SZ * H_NUM * P_DIM * S_LEN]; // [B,H,P,S]
__device__ __align__(16) __nv_bfloat16 g_vtl[B_SZ * H_NUM * P_DIM * S_LEN];
__device__ __align__(16) __nv_bfloat16 g_xh[M_ROWS * E_DIM];
__device__ __align__(16) __nv_bfloat16 g_xl[M_ROWS * E_DIM];
__device__ __align__(16) __nv_bfloat16 g_wth[4 * E_DIM * E_DIM];  // Wt[n][k], z=q,k,v,o
__device__ __align__(16) __nv_bfloat16 g_wtl[4 * E_DIM * E_DIM];
__device__ __align__(16) __nv_bfloat16 g_oh[M_ROWS * E_DIM];      // attn out hi
__device__ __align__(16) __nv_bfloat16 g_ol[M_ROWS * E_DIM];      // attn out lo

// ---------------------------------------------------------------------------
// helpers
// ---------------------------------------------------------------------------
__device__ __forceinline__ void mma16816(float c[4],
    uint32_t a0, uint32_t a1, uint32_t a2, uint32_t a3,
    uint32_t b0, uint32_t b1)
{
    asm volatile(
        "mma.sync.aligned.m16n8k16.row.col.f32.bf16.bf16.f32 "
        "{%0,%1,%2,%3}, {%4,%5,%6,%7}, {%8,%9}, {%0,%1,%2,%3};"
        : "+f"(c[0]), "+f"(c[1]), "+f"(c[2]), "+f"(c[3])
        : "r"(a0), "r"(a1), "r"(a2), "r"(a3), "r"(b0), "r"(b1));
}

__device__ __forceinline__ void ldsm_x4(uint32_t r[4], uint32_t addr) {
    asm volatile("ldmatrix.sync.aligned.m8n8.x4.shared.b16 {%0,%1,%2,%3}, [%4];"
                 : "=r"(r[0]), "=r"(r[1]), "=r"(r[2]), "=r"(r[3]) : "r"(addr));
}

__device__ __forceinline__ uint32_t smem_u32(const void* p) {
    uint32_t a;
    asm("{ .reg .u64 t; cvta.to.shared.u64 t, %1; cvt.u32.u64 %0, t; }"
        : "=r"(a) : "l"(p));
    return a;
}
__device__ __forceinline__ void cp16(uint32_t saddr, const void* g) {
    asm volatile("cp.async.cg.shared.global [%0], [%1], 16;"
                 :: "r"(saddr), "l"(g) : "memory");
}
#define CP_COMMIT() asm volatile("cp.async.commit_group;" ::: "memory")
#define CP_WAIT(N)  asm volatile("cp.async.wait_group %0;" :: "n"(N) : "memory")

__device__ __forceinline__ float ex2f(float x) {
    float y;
    asm("ex2.approx.ftz.f32 %0, %1;" : "=f"(y) : "f"(x));
    return y;
}
// pack (lo, hi) floats into bf16x2 register
__device__ __forceinline__ uint32_t pack_bf16x2(float lo, float hi) {
    uint32_t r;
    asm("cvt.rn.bf16x2.f32 %0, %1, %2;" : "=r"(r) : "f"(hi), "f"(lo));
    return r;
}
__device__ __forceinline__ void split2(float v, __nv_bfloat16& h, __nv_bfloat16& l) {
    h = __float2bfloat16(v);
    l = __float2bfloat16(v - __bfloat162float(h));
}

// ---------------------------------------------------------------------------
// Prep (merged): blocks [0,864) split x; blocks [864,1120) transpose+split W.
// ---------------------------------------------------------------------------
__global__ __launch_bounds__(256) void prep_kernel(
    const float* __restrict__ x,
    const float* __restrict__ Wq, const float* __restrict__ Wk,
    const float* __restrict__ Wv, const float* __restrict__ Wo)
{
    if (blockIdx.x < 864) {
        int i = (blockIdx.x * 256 + threadIdx.x) * 4;
        float4 v = *(const float4*)&x[i];
        uint2 hi, lo;
        hi.x = pack_bf16x2(v.x, v.y);
        hi.y = pack_bf16x2(v.z, v.w);
        lo.x = pack_bf16x2(v.x - __uint_as_float(hi.x << 16),
                           v.y - __uint_as_float(hi.x & 0xffff0000u));
        lo.y = pack_bf16x2(v.z - __uint_as_float(hi.y << 16),
                           v.w - __uint_as_float(hi.y & 0xffff0000u));
        *(uint2*)&g_xh[i] = hi;
        *(uint2*)&g_xl[i] = lo;
    } else {
        __shared__ float s[32][33];
        int bid = blockIdx.x - 864;
        int z = bid >> 6, rem = bid & 63;
        int k0 = (rem & 7) * 32, n0 = (rem >> 3) * 32;
        const float* W = (z == 0) ? Wq : (z == 1) ? Wk : (z == 2) ? Wv : Wo;
        const int c = threadIdx.x & 31, r0 = threadIdx.x >> 5;
        #pragma unroll
        for (int i = 0; i < 4; i++) {
            int r = r0 + i * 8;
            s[r][c] = W[(k0 + r) * E_DIM + n0 + c];
        }
        __syncthreads();
        #pragma unroll
        for (int i = 0; i < 4; i++) {
            int r = r0 + i * 8;
            float v = s[c][r];
            __nv_bfloat16 h, l; split2(v, h, l);
            size_t idx = (size_t)z * E_DIM * E_DIM + (size_t)(n0 + r) * E_DIM + k0 + c;
            g_wth[idx] = h;
            g_wtl[idx] = l;
        }
    }
}

// ---------------------------------------------------------------------------
// Shared GEMM body: C[128,64] = A[128,256] @ Wt[64,256]^T, bf16-split 3-MMA,
// cp.async 3-stage ring + ldmatrix fragments. 256 threads (8 warps 4x2).
// ---------------------------------------------------------------------------
struct GemmFrag {
    float c[2][4][4];
};

__device__ __forceinline__ void gemm_body(
    const __nv_bfloat16* __restrict__ Agh, const __nv_bfloat16* __restrict__ Agl,
    const __nv_bfloat16* __restrict__ wth, const __nv_bfloat16* __restrict__ wtl,
    int m0, int n0, GemmFrag& F)
{
    extern __shared__ __align__(16) char smem_raw[];
    __nv_bfloat16* S = (__nv_bfloat16*)smem_raw;

    const int tid = threadIdx.x;
    const int warp = tid >> 5, lane = tid & 31;
    const int wm = warp >> 1, wn = warp & 1;

    const int ar = tid >> 2, ac = (tid & 3) * 8;
    const int br = tid >> 2, bc = (tid & 3) * 8;

    const int aoffA = (wm * 32 + (lane & 7) + ((lane >> 3) & 1) * 8) * 40 + (lane >> 4) * 8;
    const int aoffB = (wn * 32 + (lane & 7)) * 40 + (lane >> 3) * 8;

    #define GLOAD(kk, b) do {                                                  \
        int _k0 = (kk) * 32;                                                   \
        __nv_bfloat16* Ah_ = S + (b) * GBUF_ELE;                               \
        __nv_bfloat16* Al_ = Ah_ + GA_ELE;                                     \
        __nv_bfloat16* Bh_ = Al_ + GA_ELE;                                     \
        __nv_bfloat16* Bl_ = Bh_ + GB_ELE;                                     \
        cp16(smem_u32(Ah_ + ar * 40 + ac),                                     \
             &Agh[(size_t)(m0 + ar) * E_DIM + _k0 + ac]);                      \
        cp16(smem_u32(Ah_ + (ar + 64) * 40 + ac),                              \
             &Agh[(size_t)(m0 + ar + 64) * E_DIM + _k0 + ac]);                 \
        cp16(smem_u32(Al_ + ar * 40 + ac),                                     \
             &Agl[(size_t)(m0 + ar) * E_DIM + _k0 + ac]);                      \
        cp16(smem_u32(Al_ + (ar + 64) * 40 + ac),                              \
             &Agl[(size_t)(m0 + ar + 64) * E_DIM + _k0 + ac]);                 \
        cp16(smem_u32(Bh_ + br * 40 + bc),                                     \
             &wth[(size_t)(n0 + br) * E_DIM + _k0 + bc]);                      \
        cp16(smem_u32(Bl_ + br * 40 + bc),                                     \
             &wtl[(size_t)(n0 + br) * E_DIM + _k0 + bc]);                      \
    } while (0)

    GLOAD(0, 0); CP_COMMIT();
    GLOAD(1, 1); CP_COMMIT();

    #pragma unroll
    for (int mf = 0; mf < 2; mf++)
        #pragma unroll
        for (int nf = 0; nf < 4; nf++)
            #pragma unroll
            for (int i = 0; i < 4; i++)
                F.c[mf][nf][i] = 0.f;

    for (int kk = 0; kk < 8; kk++) {
        const int b = kk % 3;
        CP_WAIT(1);
        __syncthreads();
        if (kk + 2 < 8) { GLOAD(kk + 2, (kk + 2) % 3); CP_COMMIT(); }
        else { CP_COMMIT(); }

        __nv_bfloat16* Ah_ = S + b * GBUF_ELE;
        __nv_bfloat16* Al_ = Ah_ + GA_ELE;
        __nv_bfloat16* Bh_ = Al_ + GA_ELE;
        __nv_bfloat16* Bl_ = Bh_ + GB_ELE;
        const uint32_t aA_h = smem_u32(Ah_ + aoffA);
        const uint32_t aA_l = smem_u32(Al_ + aoffA);
        const uint32_t aB_h = smem_u32(Bh_ + aoffB);
        const uint32_t aB_l = smem_u32(Bl_ + aoffB);

        uint32_t ah[2][2][4], al[2][2][4];
        #pragma unroll
        for (int mf = 0; mf < 2; mf++) {
            #pragma unroll
            for (int ks = 0; ks < 2; ks++) {
                ldsm_x4(ah[mf][ks], aA_h + mf * (16 * 80) + ks * 32);
                ldsm_x4(al[mf][ks], aA_l + mf * (16 * 80) + ks * 32);
            }
        }
        #pragma unroll
        for (int nf = 0; nf < 4; nf++) {
            uint32_t bh4[4], bl4[4];
            ldsm_x4(bh4, aB_h + nf * (8 * 80));
            ldsm_x4(bl4, aB_l + nf * (8 * 80));
            #pragma unroll
            for (int mf = 0; mf < 2; mf++) {
                #pragma unroll
                for (int ks = 0; ks < 2; ks++) {
                    uint32_t b0h = bh4[2 * ks], b1h = bh4[2 * ks + 1];
                    uint32_t b0l = bl4[2 * ks], b1l = bl4[2 * ks + 1];
                    mma16816(F.c[mf][nf], ah[mf][ks][0], ah[mf][ks][1],
                             ah[mf][ks][2], ah[mf][ks][3], b0h, b1h);
                    mma16816(F.c[mf][nf], al[mf][ks][0], al[mf][ks][1],
                             al[mf][ks][2], al[mf][ks][3], b0h, b1h);
                    mma16816(F.c[mf][nf], ah[mf][ks][0], ah[mf][ks][1],
                             ah[mf][ks][2], ah[mf][ks][3], b0l, b1l);
                }
            }
        }
    }
    CP_WAIT(0);
    #undef GLOAD
}

// ---------------------------------------------------------------------------
// Kernel 1: QKV projection. grid (27, 4, 3), block 256, dynamic smem ring.
// ---------------------------------------------------------------------------
__global__ __launch_bounds__(256) void qkv_mma_kernel(
    const float* __restrict__ bq, const float* __restrict__ bk,
    const float* __restrict__ bv)
{
    const int tid = threadIdx.x;
    const int warp = tid >> 5, lane = tid & 31;
    const int g = lane >> 2, tig = lane & 3;
    const int wm = warp >> 1, wn = warp & 1;
    const int m0 = blockIdx.x * 128;
    const int n0 = blockIdx.y * 64;
    const int z  = blockIdx.z;

    const __nv_bfloat16* wth = g_wth + (size_t)z * E_DIM * E_DIM;
    const __nv_bfloat16* wtl = g_wtl + (size_t)z * E_DIM * E_DIM;
    const float* bias = (z == 0) ? bq : (z == 1) ? bk : bv;
    const float outscale = (z == 0) ? LOG2E : 1.0f;

    GemmFrag F;
    gemm_body(g_xh, g_xl, wth, wtl, m0, n0, F);

    #pragma unroll
    for (int mf = 0; mf < 2; mf++) {
        int rr[2] = { m0 + wm * 32 + mf * 16 + g, m0 + wm * 32 + mf * 16 + g + 8 };
        #pragma unroll
        for (int nf = 0; nf < 4; nf++) {
            int n = n0 + wn * 32 + nf * 8 + 2 * tig;
            int h = n >> 5, p = n & 31;
            float b0 = bias[n], b1 = bias[n + 1];
            #pragma unroll
            for (int half = 0; half < 2; half++) {
                int m = rr[half];
                int bb = m / S_LEN, s = m % S_LEN;
                float v0 = (F.c[mf][nf][2 * half] + b0) * outscale;
                float v1 = (F.c[mf][nf][2 * half + 1] + b1) * outscale;
                __nv_bfloat16 h0, l0, h1, l1;
                split2(v0, h0, l0); split2(v1, h1, l1);
                if (z == 2) {
                    size_t tb = ((size_t)(bb * H_NUM + h) * P_DIM + p) * S_LEN + s;
                    g_vth[tb] = h0; g_vth[tb + S_LEN] = h1;
                    g_vtl[tb] = l0; g_vtl[tb + S_LEN] = l1;
                } else {
                    size_t idx = ((size_t)(bb * H_NUM + h) * S_LEN + s) * P_DIM + p;
                    uint32_t ph = ((uint32_t)__bfloat16_as_ushort(h1) << 16) |
                                  __bfloat16_as_ushort(h0);
                    uint32_t pl = ((uint32_t)__bfloat16_as_ushort(l1) << 16) |
                                  __bfloat16_as_ushort(l0);
                    if (z == 0) { *(uint32_t*)&g_qh[idx] = ph; *(uint32_t*)&g_ql[idx] = pl; }
                    else        { *(uint32_t*)&g_kh[idx] = ph; *(uint32_t*)&g_kl[idx] = pl; }
                }
            }
        }
    }
}

// ---------------------------------------------------------------------------
// Kernel 3: output projection. grid (27, 4), block 256, dynamic smem ring.
// ---------------------------------------------------------------------------
__global__ __launch_bounds__(256) void out_mma_kernel(
    const float* __restrict__ bo, float* __restrict__ out)
{
    const int tid = threadIdx.x;
    const int warp = tid >> 5, lane = tid & 31;
    const int g = lane >> 2, tig = lane & 3;
    const int wm = warp >> 1, wn = warp & 1;
    const int m0 = blockIdx.x * 128;
    const int n0 = blockIdx.y * 64;

    const __nv_bfloat16* wth = g_wth + (size_t)3 * E_DIM * E_DIM;
    const __nv_bfloat16* wtl = g_wtl + (size_t)3 * E_DIM * E_DIM;

    GemmFrag F;
    gemm_body(g_oh, g_ol, wth, wtl, m0, n0, F);

    #pragma unroll
    for (int mf = 0; mf < 2; mf++) {
        int r0 = m0 + wm * 32 + mf * 16 + g;
        int r1 = r0 + 8;
        #pragma unroll
        for (int nf = 0; nf < 4; nf++) {
            int n = n0 + wn * 32 + nf * 8 + 2 * tig;
            float b0 = bo[n], b1 = bo[n + 1];
            *(float2*)&out[(size_t)r0 * E_DIM + n] =
                make_float2(F.c[mf][nf][0] + b0, F.c[mf][nf][1] + b1);
            *(float2*)&out[(size_t)r1 * E_DIM + n] =
                make_float2(F.c[mf][nf][2] + b0, F.c[mf][nf][3] + b1);
        }
    }
}

// ---------------------------------------------------------------------------
// Kernel 2: flash attention (R12/R13 structure; QT=96, 6 warps, 2 CTA/SM).
// Score accumulation split into two independent MMA chains for ILP.
// ---------------------------------------------------------------------------
__global__ __launch_bounds__(ATT, 2) void attn_mma_kernel()
{
    __shared__ __nv_bfloat16 Kh[2][KN][40], Kl[2][KN][40];
    __shared__ __nv_bfloat16 Vth[2][P_DIM][72], Vtl[2][P_DIM][72];

    const int tid  = threadIdx.x;
    const int warp = tid >> 5, lane = tid & 31;
    const int g    = lane >> 2, tig = lane & 3;
    const int l8   = lane & 7, lq = lane >> 3;
    const int woff = warp * 16;
    const int bh   = blockIdx.y;
    const int q0   = blockIdx.x * QT;

    const size_t bhSP = (size_t)bh * S_LEN * P_DIM;
    const size_t bhPS = (size_t)bh * P_DIM * S_LEN;

    uint32_t aKh[2], aKl[2], aVh[2], aVl[2];
    #pragma unroll
    for (int b = 0; b < 2; b++) {
        aKh[b] = smem_u32(&Kh[b][l8][8 * lq]);
        aKl[b] = smem_u32(&Kl[b][l8][8 * lq]);
        aVh[b] = smem_u32(&Vth[b][l8][8 * lq]);
        aVl[b] = smem_u32(&Vtl[b][l8][8 * lq]);
    }

    #define LOAD_TILE(kt, b) do {                                               \
        int _k0 = (kt) * KN;                                                    \
        for (int i = tid; i < KN * 4; i += ATT) {                               \
            int r = i >> 2, c = (i & 3) * 8;                                    \
            cp16(smem_u32(&Kh[b][r][c]),                                        \
                 &g_kh[bhSP + (size_t)(_k0 + r) * P_DIM + c]);                  \
            cp16(smem_u32(&Kl[b][r][c]),                                        \
                 &g_kl[bhSP + (size_t)(_k0 + r) * P_DIM + c]);                  \
        }                                                                       \
        for (int i = tid; i < P_DIM * 8; i += ATT) {                            \
            int p = i >> 3, c = (i & 7) * 8;                                    \
            cp16(smem_u32(&Vth[b][p][c]),                                       \
                 &g_vth[bhPS + (size_t)p * S_LEN + _k0 + c]);                   \
            cp16(smem_u32(&Vtl[b][p][c]),                                       \
                 &g_vtl[bhPS + (size_t)p * S_LEN + _k0 + c]);                   \
        }                                                                       \
    } while (0)

    LOAD_TILE(0, 0);
    CP_COMMIT();

    const int r0g = q0 + woff + g;
    const size_t qb0 = bhSP + (size_t)r0g * P_DIM;
    const size_t qb1 = qb0 + 8 * P_DIM;
    uint32_t qh[2][4], ql[2][4];
    #pragma unroll
    for (int ks = 0; ks < 2; ks++) {
        int p0 = ks * 16 + 2 * tig;
        qh[ks][0] = *(const uint32_t*)&g_qh[qb0 + p0];
        qh[ks][1] = *(const uint32_t*)&g_qh[qb1 + p0];
        qh[ks][2] = *(const uint32_t*)&g_qh[qb0 + p0 + 8];
        qh[ks][3] = *(const uint32_t*)&g_qh[qb1 + p0 + 8];
        ql[ks][0] = *(const uint32_t*)&g_ql[qb0 + p0];
        ql[ks][1] = *(const uint32_t*)&g_ql[qb1 + p0];
        ql[ks][2] = *(const uint32_t*)&g_ql[qb0 + p0 + 8];
        ql[ks][3] = *(const uint32_t*)&g_ql[qb1 + p0 + 8];
    }

    float o[4][4] = {};
    float l0 = 0.f, l1 = 0.f;

    for (int kt = 0; kt < NKT; kt++) {
        const int buf = kt & 1;
        if (kt + 1 < NKT) {
            LOAD_TILE(kt + 1, buf ^ 1);
            CP_COMMIT();
            CP_WAIT(1);
        } else {
            CP_WAIT(0);
        }
        __syncthreads();

        uint32_t phi01[8], phi23[8], plo01[8], plo23[8];
        #pragma unroll
        for (int nt = 0; nt < 8; nt++) {
            uint32_t kh4[4], kl4[4];
            ldsm_x4(kh4, aKh[buf] + nt * (8 * 40 * 2));
            ldsm_x4(kl4, aKl[buf] + nt * (8 * 40 * 2));
            // two independent accumulation chains (depth 2 and 4), merged
            float cA[4] = {0.f, 0.f, 0.f, 0.f};
            float cB[4] = {0.f, 0.f, 0.f, 0.f};
            mma16816(cA, qh[0][0], qh[0][1], qh[0][2], qh[0][3], kh4[0], kh4[1]);
            mma16816(cB, ql[0][0], ql[0][1], ql[0][2], ql[0][3], kh4[0], kh4[1]);
            mma16816(cA, qh[1][0], qh[1][1], qh[1][2], qh[1][3], kh4[2], kh4[3]);
            mma16816(cB, qh[0][0], qh[0][1], qh[0][2], qh[0][3], kl4[0], kl4[1]);
            mma16816(cB, ql[1][0], ql[1][1], ql[1][2], ql[1][3], kh4[2], kh4[3]);
            mma16816(cB, qh[1][0], qh[1][1], qh[1][2], qh[1][3], kl4[2], kl4[3]);

            float e0 = ex2f(cA[0] + cB[0]);
            float e1 = ex2f(cA[1] + cB[1]);
            float e2 = ex2f(cA[2] + cB[2]);
            float e3 = ex2f(cA[3] + cB[3]);
            l0 += e0 + e1;
            l1 += e2 + e3;
            uint32_t ph01 = pack_bf16x2(e0, e1);
            uint32_t ph23 = pack_bf16x2(e2, e3);
            phi01[nt] = ph01;
            phi23[nt] = ph23;
            plo01[nt] = pack_bf16x2(e0 - __uint_as_float(ph01 << 16),
                                    e1 - __uint_as_float(ph01 & 0xffff0000u));
            plo23[nt] = pack_bf16x2(e2 - __uint_as_float(ph23 << 16),
                                    e3 - __uint_as_float(ph23 & 0xffff0000u));
        }

        #pragma unroll
        for (int n = 0; n < 4; n++) {
            uint32_t vhA[4], vhB[4], vlA[4], vlB[4];
            uint32_t base = n * (8 * 72 * 2);
            ldsm_x4(vhA, aVh[buf] + base);
            ldsm_x4(vhB, aVh[buf] + base + 64);
            ldsm_x4(vlA, aVl[buf] + base);
            ldsm_x4(vlB, aVl[buf] + base + 64);
            #pragma unroll
            for (int ks = 0; ks < 4; ks++) {
                uint32_t b0h = (ks < 2 ? vhA : vhB)[2 * (ks & 1)];
                uint32_t b1h = (ks < 2 ? vhA : vhB)[2 * (ks & 1) + 1];
                uint32_t b0l = (ks < 2 ? vlA : vlB)[2 * (ks & 1)];
                uint32_t b1l = (ks < 2 ? vlA : vlB)[2 * (ks & 1) + 1];
                uint32_t a0 = phi01[2 * ks], a1 = phi23[2 * ks];
                uint32_t a2 = phi01[2 * ks + 1], a3 = phi23[2 * ks + 1];
                mma16816(o[n], a0, a1, a2, a3, b0h, b1h);
                mma16816(o[n], a0, a1, a2, a3, b0l, b1l);
                mma16816(o[n], plo01[2 * ks], plo23[2 * ks],
                               plo01[2 * ks + 1], plo23[2 * ks + 1], b0h, b1h);
            }
        }
        __syncthreads();
    }

    l0 += __shfl_xor_sync(0xffffffffu, l0, 1);
    l0 += __shfl_xor_sync(0xffffffffu, l0, 2);
    l1 += __shfl_xor_sync(0xffffffffu, l1, 1);
    l1 += __shfl_xor_sync(0xffffffffu, l1, 2);
    const float inv0 = 1.0f / l0;
    const float inv1 = 1.0f / l1;

    const int b = bh >> 3, h = bh & 7;
    const int r1g = r0g + 8;
    #pragma unroll
    for (int n = 0; n < 4; n++) {
        int p = 8 * n + 2 * tig;
        {
            float w0 = o[n][0] * inv0, w1 = o[n][1] * inv0;
            size_t idx = ((size_t)b * S_LEN + r0g) * E_DIM + h * P_DIM + p;
            uint32_t ph = pack_bf16x2(w0, w1);
            *(uint32_t*)&g_oh[idx] = ph;
            *(uint32_t*)&g_ol[idx] = pack_bf16x2(w0 - __uint_as_float(ph << 16),
                                                 w1 - __uint_as_float(ph & 0xffff0000u));
        }
        {
            float w0 = o[n][2] * inv1, w1 = o[n][3] * inv1;
            size_t idx = ((size_t)b * S_LEN + r1g) * E_DIM + h * P_DIM + p;
            uint32_t ph = pack_bf16x2(w0, w1);
            *(uint32_t*)&g_oh[idx] = ph;
            *(uint32_t*)&g_ol[idx] = pack_bf16x2(w0 - __uint_as_float(ph << 16),
                                                 w1 - __uint_as_float(ph & 0xffff0000u));
        }
    }
}

extern "C" void kernel_launch(void* const* d_in, const int* in_sizes, int n_in,
                              void* d_out, int out_size)
{
    const float* x  = (const float*)d_in[0];
    const float* bq = (const float*)d_in[2];
    const float* bk = (const float*)d_in[4];
    const float* bv = (const float*)d_in[6];
    const float* bo = (const float*)d_in[8];
    float* out = (float*)d_out;

    static bool attr_set = false;
    if (!attr_set) {
        cudaFuncSetAttribute(qkv_mma_kernel,
            cudaFuncAttributeMaxDynamicSharedMemorySize, GEMM_SMEM_BYTES);
        cudaFuncSetAttribute(out_mma_kernel,
            cudaFuncAttributeMaxDynamicSharedMemorySize, GEMM_SMEM_BYTES);
        attr_set = true;
    }

    prep_kernel<<<1120, 256>>>(x,
        (const float*)d_in[1], (const float*)d_in[3],
        (const float*)d_in[5], (const float*)d_in[7]);
    qkv_mma_kernel<<<dim3(27, 4, 3), 256, GEMM_SMEM_BYTES>>>(bq, bk, bv);
    attn_mma_kernel<<<dim3(18, 16), ATT>>>();
    out_mma_kernel<<<dim3(27, 4), 256, GEMM_SMEM_BYTES>>>(bo, out);
}

// round 17
// speedup vs baseline: 1.4481x; 1.0232x over previous
#include <cuda_runtime.h>
#include <cuda_bf16.h>
#include <cstdint>

#define S_LEN 1728
#define B_SZ 2
#define E_DIM 256
#define H_NUM 8
#define P_DIM 32
#define M_ROWS (B_SZ * S_LEN)   // 3456

#define QT 96                   // q rows per block (attn): 18 tiles exactly
#define ATW 6                   // attn warps per block
#define ATT (ATW * 32)          // 192 threads
#define KN 64                   // keys per tile (attn)
#define NKT (S_LEN / KN)        // 27

#define LOG2E 1.44269504088896340736f

// GEMM smem ring geometry (elements) — M tile 64
#define GA_ELE (64 * 40)
#define GB_ELE (64 * 40)
#define GBUF_ELE (2 * GA_ELE + 2 * GB_ELE)          // Ah,Al,Bh,Bl = 10240 ele
#define GEMM_SMEM_BYTES (3 * GBUF_ELE * 2)          // 3-stage ring = 61440 B

// split-bf16 scratch (no allocations allowed)
__device__ __align__(16) __nv_bfloat16 g_qh[B_SZ * H_NUM * S_LEN * P_DIM]; // [B,H,S,P]
__device__ __align__(16) __nv_bfloat16 g_ql[B_SZ * H_NUM * S_LEN * P_DIM];
__device__ __align__(16) __nv_bfloat16 g_kh[B_SZ * H_NUM * S_LEN * P_DIM];
__device__ __align__(16) __nv_bfloat16 g_kl[B_SZ * H_NUM * S_LEN * P_DIM];
__device__ __align__(16) __nv_bfloat16 g_vth[B_SZ * H_NUM * P_DIM * S_LEN]; // [B,H,P,S]
__device__ __align__(16) __nv_bfloat16 g_vtl[B_SZ * H_NUM * P_DIM * S_LEN];
__device__ __align__(16) __nv_bfloat16 g_xh[M_ROWS * E_DIM];
__device__ __align__(16) __nv_bfloat16 g_xl[M_ROWS * E_DIM];
__device__ __align__(16) __nv_bfloat16 g_wth[4 * E_DIM * E_DIM];  // Wt[n][k], z=q,k,v,o
__device__ __align__(16) __nv_bfloat16 g_wtl[4 * E_DIM * E_DIM];
__device__ __align__(16) __nv_bfloat16 g_oh[M_ROWS * E_DIM];      // attn out hi
__device__ __align__(16) __nv_bfloat16 g_ol[M_ROWS * E_DIM];      // attn out lo

// ---------------------------------------------------------------------------
// helpers
// ---------------------------------------------------------------------------
__device__ __forceinline__ void mma16816(float c[4],
    uint32_t a0, uint32_t a1, uint32_t a2, uint32_t a3,
    uint32_t b0, uint32_t b1)
{
    asm volatile(
        "mma.sync.aligned.m16n8k16.row.col.f32.bf16.bf16.f32 "
        "{%0,%1,%2,%3}, {%4,%5,%6,%7}, {%8,%9}, {%0,%1,%2,%3};"
        : "+f"(c[0]), "+f"(c[1]), "+f"(c[2]), "+f"(c[3])
        : "r"(a0), "r"(a1), "r"(a2), "r"(a3), "r"(b0), "r"(b1));
}

__device__ __forceinline__ void ldsm_x4(uint32_t r[4], uint32_t addr) {
    asm volatile("ldmatrix.sync.aligned.m8n8.x4.shared.b16 {%0,%1,%2,%3}, [%4];"
                 : "=r"(r[0]), "=r"(r[1]), "=r"(r[2]), "=r"(r[3]) : "r"(addr));
}

__device__ __forceinline__ uint32_t smem_u32(const void* p) {
    uint32_t a;
    asm("{ .reg .u64 t; cvta.to.shared.u64 t, %1; cvt.u32.u64 %0, t; }"
        : "=r"(a) : "l"(p));
    return a;
}
__device__ __forceinline__ void cp16(uint32_t saddr, const void* g) {
    asm volatile("cp.async.cg.shared.global [%0], [%1], 16;"
                 :: "r"(saddr), "l"(g) : "memory");
}
#define CP_COMMIT() asm volatile("cp.async.commit_group;" ::: "memory")
#define CP_WAIT(N)  asm volatile("cp.async.wait_group %0;" :: "n"(N) : "memory")

__device__ __forceinline__ float ex2f(float x) {
    float y;
    asm("ex2.approx.ftz.f32 %0, %1;" : "=f"(y) : "f"(x));
    return y;
}
// pack (lo, hi) floats into bf16x2 register
__device__ __forceinline__ uint32_t pack_bf16x2(float lo, float hi) {
    uint32_t r;
    asm("cvt.rn.bf16x2.f32 %0, %1, %2;" : "=r"(r) : "f"(hi), "f"(lo));
    return r;
}
__device__ __forceinline__ void split2(float v, __nv_bfloat16& h, __nv_bfloat16& l) {
    h = __float2bfloat16(v);
    l = __float2bfloat16(v - __bfloat162float(h));
}

// ---------------------------------------------------------------------------
// Prep (merged): blocks [0,864) split x; blocks [864,1120) transpose+split W.
// ---------------------------------------------------------------------------
__global__ __launch_bounds__(256) void prep_kernel(
    const float* __restrict__ x,
    const float* __restrict__ Wq, const float* __restrict__ Wk,
    const float* __restrict__ Wv, const float* __restrict__ Wo)
{
    if (blockIdx.x < 864) {
        int i = (blockIdx.x * 256 + threadIdx.x) * 4;
        float4 v = *(const float4*)&x[i];
        uint2 hi, lo;
        hi.x = pack_bf16x2(v.x, v.y);
        hi.y = pack_bf16x2(v.z, v.w);
        lo.x = pack_bf16x2(v.x - __uint_as_float(hi.x << 16),
                           v.y - __uint_as_float(hi.x & 0xffff0000u));
        lo.y = pack_bf16x2(v.z - __uint_as_float(hi.y << 16),
                           v.w - __uint_as_float(hi.y & 0xffff0000u));
        *(uint2*)&g_xh[i] = hi;
        *(uint2*)&g_xl[i] = lo;
    } else {
        __shared__ float s[32][33];
        int bid = blockIdx.x - 864;
        int z = bid >> 6, rem = bid & 63;
        int k0 = (rem & 7) * 32, n0 = (rem >> 3) * 32;
        const float* W = (z == 0) ? Wq : (z == 1) ? Wk : (z == 2) ? Wv : Wo;
        const int c = threadIdx.x & 31, r0 = threadIdx.x >> 5;
        #pragma unroll
        for (int i = 0; i < 4; i++) {
            int r = r0 + i * 8;
            s[r][c] = W[(k0 + r) * E_DIM + n0 + c];
        }
        __syncthreads();
        #pragma unroll
        for (int i = 0; i < 4; i++) {
            int r = r0 + i * 8;
            float v = s[c][r];
            __nv_bfloat16 h, l; split2(v, h, l);
            size_t idx = (size_t)z * E_DIM * E_DIM + (size_t)(n0 + r) * E_DIM + k0 + c;
            g_wth[idx] = h;
            g_wtl[idx] = l;
        }
    }
}

// ---------------------------------------------------------------------------
// Shared GEMM body: C[64,64] = A[64,256] @ Wt[64,256]^T, bf16-split 3-MMA,
// cp.async 3-stage ring + ldmatrix fragments. 256 threads (8 warps = 4M x 2N,
// warp tile 16x32).
// ---------------------------------------------------------------------------
struct GemmFrag {
    float c[4][4];   // [nf][reg]
};

__device__ __forceinline__ void gemm_body(
    const __nv_bfloat16* __restrict__ Agh, const __nv_bfloat16* __restrict__ Agl,
    const __nv_bfloat16* __restrict__ wth, const __nv_bfloat16* __restrict__ wtl,
    int m0, int n0, GemmFrag& F)
{
    extern __shared__ __align__(16) char smem_raw[];
    __nv_bfloat16* S = (__nv_bfloat16*)smem_raw;

    const int tid = threadIdx.x;
    const int warp = tid >> 5, lane = tid & 31;
    const int wm = warp >> 1, wn = warp & 1;

    const int ar = tid >> 2, ac = (tid & 3) * 8;   // 64 rows x 4 chunks = 1/thread
    const int br = tid >> 2, bc = (tid & 3) * 8;

    const int aoffA = (wm * 16 + (lane & 7) + ((lane >> 3) & 1) * 8) * 40 + (lane >> 4) * 8;
    const int aoffB = (wn * 32 + (lane & 7)) * 40 + (lane >> 3) * 8;

    #define GLOAD(kk, b) do {                                                  \
        int _k0 = (kk) * 32;                                                   \
        __nv_bfloat16* Ah_ = S + (b) * GBUF_ELE;                               \
        __nv_bfloat16* Al_ = Ah_ + GA_ELE;                                     \
        __nv_bfloat16* Bh_ = Al_ + GA_ELE;                                     \
        __nv_bfloat16* Bl_ = Bh_ + GB_ELE;                                     \
        cp16(smem_u32(Ah_ + ar * 40 + ac),                                     \
             &Agh[(size_t)(m0 + ar) * E_DIM + _k0 + ac]);                      \
        cp16(smem_u32(Al_ + ar * 40 + ac),                                     \
             &Agl[(size_t)(m0 + ar) * E_DIM + _k0 + ac]);                      \
        cp16(smem_u32(Bh_ + br * 40 + bc),                                     \
             &wth[(size_t)(n0 + br) * E_DIM + _k0 + bc]);                      \
        cp16(smem_u32(Bl_ + br * 40 + bc),                                     \
             &wtl[(size_t)(n0 + br) * E_DIM + _k0 + bc]);                      \
    } while (0)

    GLOAD(0, 0); CP_COMMIT();
    GLOAD(1, 1); CP_COMMIT();

    #pragma unroll
    for (int nf = 0; nf < 4; nf++)
        #pragma unroll
        for (int i = 0; i < 4; i++)
            F.c[nf][i] = 0.f;

    for (int kk = 0; kk < 8; kk++) {
        const int b = kk % 3;
        CP_WAIT(1);
        __syncthreads();
        if (kk + 2 < 8) { GLOAD(kk + 2, (kk + 2) % 3); CP_COMMIT(); }
        else { CP_COMMIT(); }

        __nv_bfloat16* Ah_ = S + b * GBUF_ELE;
        __nv_bfloat16* Al_ = Ah_ + GA_ELE;
        __nv_bfloat16* Bh_ = Al_ + GA_ELE;
        __nv_bfloat16* Bl_ = Bh_ + GB_ELE;
        const uint32_t aA_h = smem_u32(Ah_ + aoffA);
        const uint32_t aA_l = smem_u32(Al_ + aoffA);
        const uint32_t aB_h = smem_u32(Bh_ + aoffB);
        const uint32_t aB_l = smem_u32(Bl_ + aoffB);

        uint32_t ah[2][4], al[2][4];
        #pragma unroll
        for (int ks = 0; ks < 2; ks++) {
            ldsm_x4(ah[ks], aA_h + ks * 32);
            ldsm_x4(al[ks], aA_l + ks * 32);
        }
        #pragma unroll
        for (int nf = 0; nf < 4; nf++) {
            uint32_t bh4[4], bl4[4];
            ldsm_x4(bh4, aB_h + nf * (8 * 80));
            ldsm_x4(bl4, aB_l + nf * (8 * 80));
            #pragma unroll
            for (int ks = 0; ks < 2; ks++) {
                uint32_t b0h = bh4[2 * ks], b1h = bh4[2 * ks + 1];
                uint32_t b0l = bl4[2 * ks], b1l = bl4[2 * ks + 1];
                mma16816(F.c[nf], ah[ks][0], ah[ks][1], ah[ks][2], ah[ks][3], b0h, b1h);
                mma16816(F.c[nf], al[ks][0], al[ks][1], al[ks][2], al[ks][3], b0h, b1h);
                mma16816(F.c[nf], ah[ks][0], ah[ks][1], ah[ks][2], ah[ks][3], b0l, b1l);
            }
        }
    }
    CP_WAIT(0);
    #undef GLOAD
}

// ---------------------------------------------------------------------------
// Kernel 1: QKV projection. grid (54, 4, 3), block 256, dynamic smem ring.
// ---------------------------------------------------------------------------
__global__ __launch_bounds__(256) void qkv_mma_kernel(
    const float* __restrict__ bq, const float* __restrict__ bk,
    const float* __restrict__ bv)
{
    const int tid = threadIdx.x;
    const int warp = tid >> 5, lane = tid & 31;
    const int g = lane >> 2, tig = lane & 3;
    const int wm = warp >> 1, wn = warp & 1;
    const int m0 = blockIdx.x * 64;
    const int n0 = blockIdx.y * 64;
    const int z  = blockIdx.z;

    const __nv_bfloat16* wth = g_wth + (size_t)z * E_DIM * E_DIM;
    const __nv_bfloat16* wtl = g_wtl + (size_t)z * E_DIM * E_DIM;
    const float* bias = (z == 0) ? bq : (z == 1) ? bk : bv;
    const float outscale = (z == 0) ? LOG2E : 1.0f;

    GemmFrag F;
    gemm_body(g_xh, g_xl, wth, wtl, m0, n0, F);

    int rr[2] = { m0 + wm * 16 + g, m0 + wm * 16 + g + 8 };
    #pragma unroll
    for (int nf = 0; nf < 4; nf++) {
        int n = n0 + wn * 32 + nf * 8 + 2 * tig;
        int h = n >> 5, p = n & 31;
        float b0 = bias[n], b1 = bias[n + 1];
        #pragma unroll
        for (int half = 0; half < 2; half++) {
            int m = rr[half];
            int bb = m / S_LEN, s = m % S_LEN;
            float v0 = (F.c[nf][2 * half] + b0) * outscale;
            float v1 = (F.c[nf][2 * half + 1] + b1) * outscale;
            __nv_bfloat16 h0, l0, h1, l1;
            split2(v0, h0, l0); split2(v1, h1, l1);
            if (z == 2) {
                size_t tb = ((size_t)(bb * H_NUM + h) * P_DIM + p) * S_LEN + s;
                g_vth[tb] = h0; g_vth[tb + S_LEN] = h1;
                g_vtl[tb] = l0; g_vtl[tb + S_LEN] = l1;
            } else {
                size_t idx = ((size_t)(bb * H_NUM + h) * S_LEN + s) * P_DIM + p;
                uint32_t ph = ((uint32_t)__bfloat16_as_ushort(h1) << 16) |
                              __bfloat16_as_ushort(h0);
                uint32_t pl = ((uint32_t)__bfloat16_as_ushort(l1) << 16) |
                              __bfloat16_as_ushort(l0);
                if (z == 0) { *(uint32_t*)&g_qh[idx] = ph; *(uint32_t*)&g_ql[idx] = pl; }
                else        { *(uint32_t*)&g_kh[idx] = ph; *(uint32_t*)&g_kl[idx] = pl; }
            }
        }
    }
}

// ---------------------------------------------------------------------------
// Kernel 3: output projection. grid (54, 4), block 256, dynamic smem ring.
// ---------------------------------------------------------------------------
__global__ __launch_bounds__(256) void out_mma_kernel(
    const float* __restrict__ bo, float* __restrict__ out)
{
    const int tid = threadIdx.x;
    const int warp = tid >> 5, lane = tid & 31;
    const int g = lane >> 2, tig = lane & 3;
    const int wm = warp >> 1, wn = warp & 1;
    const int m0 = blockIdx.x * 64;
    const int n0 = blockIdx.y * 64;

    const __nv_bfloat16* wth = g_wth + (size_t)3 * E_DIM * E_DIM;
    const __nv_bfloat16* wtl = g_wtl + (size_t)3 * E_DIM * E_DIM;

    GemmFrag F;
    gemm_body(g_oh, g_ol, wth, wtl, m0, n0, F);

    int r0 = m0 + wm * 16 + g;
    int r1 = r0 + 8;
    #pragma unroll
    for (int nf = 0; nf < 4; nf++) {
        int n = n0 + wn * 32 + nf * 8 + 2 * tig;
        float b0 = bo[n], b1 = bo[n + 1];
        *(float2*)&out[(size_t)r0 * E_DIM + n] =
            make_float2(F.c[nf][0] + b0, F.c[nf][1] + b1);
        *(float2*)&out[(size_t)r1 * E_DIM + n] =
            make_float2(F.c[nf][2] + b0, F.c[nf][3] + b1);
    }
}

// ---------------------------------------------------------------------------
// Kernel 2: flash attention (unchanged from R16; QT=96, 6 warps, 2 CTA/SM).
// ---------------------------------------------------------------------------
__global__ __launch_bounds__(ATT, 2) void attn_mma_kernel()
{
    __shared__ __nv_bfloat16 Kh[2][KN][40], Kl[2][KN][40];
    __shared__ __nv_bfloat16 Vth[2][P_DIM][72], Vtl[2][P_DIM][72];

    const int tid  = threadIdx.x;
    const int warp = tid >> 5, lane = tid & 31;
    const int g    = lane >> 2, tig = lane & 3;
    const int l8   = lane & 7, lq = lane >> 3;
    const int woff = warp * 16;
    const int bh   = blockIdx.y;
    const int q0   = blockIdx.x * QT;

    const size_t bhSP = (size_t)bh * S_LEN * P_DIM;
    const size_t bhPS = (size_t)bh * P_DIM * S_LEN;

    uint32_t aKh[2], aKl[2], aVh[2], aVl[2];
    #pragma unroll
    for (int b = 0; b < 2; b++) {
        aKh[b] = smem_u32(&Kh[b][l8][8 * lq]);
        aKl[b] = smem_u32(&Kl[b][l8][8 * lq]);
        aVh[b] = smem_u32(&Vth[b][l8][8 * lq]);
        aVl[b] = smem_u32(&Vtl[b][l8][8 * lq]);
    }

    #define LOAD_TILE(kt, b) do {                                               \
        int _k0 = (kt) * KN;                                                    \
        for (int i = tid; i < KN * 4; i += ATT) {                               \
            int r = i >> 2, c = (i & 3) * 8;                                    \
            cp16(smem_u32(&Kh[b][r][c]),                                        \
                 &g_kh[bhSP + (size_t)(_k0 + r) * P_DIM + c]);                  \
            cp16(smem_u32(&Kl[b][r][c]),                                        \
                 &g_kl[bhSP + (size_t)(_k0 + r) * P_DIM + c]);                  \
        }                                                                       \
        for (int i = tid; i < P_DIM * 8; i += ATT) {                            \
            int p = i >> 3, c = (i & 7) * 8;                                    \
            cp16(smem_u32(&Vth[b][p][c]),                                       \
                 &g_vth[bhPS + (size_t)p * S_LEN + _k0 + c]);                   \
            cp16(smem_u32(&Vtl[b][p][c]),                                       \
                 &g_vtl[bhPS + (size_t)p * S_LEN + _k0 + c]);                   \
        }                                                                       \
    } while (0)

    LOAD_TILE(0, 0);
    CP_COMMIT();

    const int r0g = q0 + woff + g;
    const size_t qb0 = bhSP + (size_t)r0g * P_DIM;
    const size_t qb1 = qb0 + 8 * P_DIM;
    uint32_t qh[2][4], ql[2][4];
    #pragma unroll
    for (int ks = 0; ks < 2; ks++) {
        int p0 = ks * 16 + 2 * tig;
        qh[ks][0] = *(const uint32_t*)&g_qh[qb0 + p0];
        qh[ks][1] = *(const uint32_t*)&g_qh[qb1 + p0];
        qh[ks][2] = *(const uint32_t*)&g_qh[qb0 + p0 + 8];
        qh[ks][3] = *(const uint32_t*)&g_qh[qb1 + p0 + 8];
        ql[ks][0] = *(const uint32_t*)&g_ql[qb0 + p0];
        ql[ks][1] = *(const uint32_t*)&g_ql[qb1 + p0];
        ql[ks][2] = *(const uint32_t*)&g_ql[qb0 + p0 + 8];
        ql[ks][3] = *(const uint32_t*)&g_ql[qb1 + p0 + 8];
    }

    float o[4][4] = {};
    float l0 = 0.f, l1 = 0.f;

    for (int kt = 0; kt < NKT; kt++) {
        const int buf = kt & 1;
        if (kt + 1 < NKT) {
            LOAD_TILE(kt + 1, buf ^ 1);
            CP_COMMIT();
            CP_WAIT(1);
        } else {
            CP_WAIT(0);
        }
        __syncthreads();

        uint32_t phi01[8], phi23[8], plo01[8], plo23[8];
        #pragma unroll
        for (int nt = 0; nt < 8; nt++) {
            uint32_t kh4[4], kl4[4];
            ldsm_x4(kh4, aKh[buf] + nt * (8 * 40 * 2));
            ldsm_x4(kl4, aKl[buf] + nt * (8 * 40 * 2));
            float cA[4] = {0.f, 0.f, 0.f, 0.f};
            float cB[4] = {0.f, 0.f, 0.f, 0.f};
            mma16816(cA, qh[0][0], qh[0][1], qh[0][2], qh[0][3], kh4[0], kh4[1]);
            mma16816(cB, ql[0][0], ql[0][1], ql[0][2], ql[0][3], kh4[0], kh4[1]);
            mma16816(cA, qh[1][0], qh[1][1], qh[1][2], qh[1][3], kh4[2], kh4[3]);
            mma16816(cB, qh[0][0], qh[0][1], qh[0][2], qh[0][3], kl4[0], kl4[1]);
            mma16816(cB, ql[1][0], ql[1][1], ql[1][2], ql[1][3], kh4[2], kh4[3]);
            mma16816(cB, qh[1][0], qh[1][1], qh[1][2], qh[1][3], kl4[2], kl4[3]);

            float e0 = ex2f(cA[0] + cB[0]);
            float e1 = ex2f(cA[1] + cB[1]);
            float e2 = ex2f(cA[2] + cB[2]);
            float e3 = ex2f(cA[3] + cB[3]);
            l0 += e0 + e1;
            l1 += e2 + e3;
            uint32_t ph01 = pack_bf16x2(e0, e1);
            uint32_t ph23 = pack_bf16x2(e2, e3);
            phi01[nt] = ph01;
            phi23[nt] = ph23;
            plo01[nt] = pack_bf16x2(e0 - __uint_as_float(ph01 << 16),
                                    e1 - __uint_as_float(ph01 & 0xffff0000u));
            plo23[nt] = pack_bf16x2(e2 - __uint_as_float(ph23 << 16),
                                    e3 - __uint_as_float(ph23 & 0xffff0000u));
        }

        #pragma unroll
        for (int n = 0; n < 4; n++) {
            uint32_t vhA[4], vhB[4], vlA[4], vlB[4];
            uint32_t base = n * (8 * 72 * 2);
            ldsm_x4(vhA, aVh[buf] + base);
            ldsm_x4(vhB, aVh[buf] + base + 64);
            ldsm_x4(vlA, aVl[buf] + base);
            ldsm_x4(vlB, aVl[buf] + base + 64);
            #pragma unroll
            for (int ks = 0; ks < 4; ks++) {
                uint32_t b0h = (ks < 2 ? vhA : vhB)[2 * (ks & 1)];
                uint32_t b1h = (ks < 2 ? vhA : vhB)[2 * (ks & 1) + 1];
                uint32_t b0l = (ks < 2 ? vlA : vlB)[2 * (ks & 1)];
                uint32_t b1l = (ks < 2 ? vlA : vlB)[2 * (ks & 1) + 1];
                uint32_t a0 = phi01[2 * ks], a1 = phi23[2 * ks];
                uint32_t a2 = phi01[2 * ks + 1], a3 = phi23[2 * ks + 1];
                mma16816(o[n], a0, a1, a2, a3, b0h, b1h);
                mma16816(o[n], a0, a1, a2, a3, b0l, b1l);
                mma16816(o[n], plo01[2 * ks], plo23[2 * ks],
                               plo01[2 * ks + 1], plo23[2 * ks + 1], b0h, b1h);
            }
        }
        __syncthreads();
    }

    l0 += __shfl_xor_sync(0xffffffffu, l0, 1);
    l0 += __shfl_xor_sync(0xffffffffu, l0, 2);
    l1 += __shfl_xor_sync(0xffffffffu, l1, 1);
    l1 += __shfl_xor_sync(0xffffffffu, l1, 2);
    const float inv0 = 1.0f / l0;
    const float inv1 = 1.0f / l1;

    const int b = bh >> 3, h = bh & 7;
    const int r1g = r0g + 8;
    #pragma unroll
    for (int n = 0; n < 4; n++) {
        int p = 8 * n + 2 * tig;
        {
            float w0 = o[n][0] * inv0, w1 = o[n][1] * inv0;
            size_t idx = ((size_t)b * S_LEN + r0g) * E_DIM + h * P_DIM + p;
            uint32_t ph = pack_bf16x2(w0, w1);
            *(uint32_t*)&g_oh[idx] = ph;
            *(uint32_t*)&g_ol[idx] = pack_bf16x2(w0 - __uint_as_float(ph << 16),
                                                 w1 - __uint_as_float(ph & 0xffff0000u));
        }
        {
            float w0 = o[n][2] * inv1, w1 = o[n][3] * inv1;
            size_t idx = ((size_t)b * S_LEN + r1g) * E_DIM + h * P_DIM + p;
            uint32_t ph = pack_bf16x2(w0, w1);
            *(uint32_t*)&g_oh[idx] = ph;
            *(uint32_t*)&g_ol[idx] = pack_bf16x2(w0 - __uint_as_float(ph << 16),
                                                 w1 - __uint_as_float(ph & 0xffff0000u));
        }
    }
}

extern "C" void kernel_launch(void* const* d_in, const int* in_sizes, int n_in,
                              void* d_out, int out_size)
{
    const float* x  = (const float*)d_in[0];
    const float* bq = (const float*)d_in[2];
    const float* bk = (const float*)d_in[4];
    const float* bv = (const float*)d_in[6];
    const float* bo = (const float*)d_in[8];
    float* out = (float*)d_out;

    static bool attr_set = false;
    if (!attr_set) {
        cudaFuncSetAttribute(qkv_mma_kernel,
            cudaFuncAttributeMaxDynamicSharedMemorySize, GEMM_SMEM_BYTES);
        cudaFuncSetAttribute(out_mma_kernel,
            cudaFuncAttributeMaxDynamicSharedMemorySize, GEMM_SMEM_BYTES);
        attr_set = true;
    }

    prep_kernel<<<1120, 256>>>(x,
        (const float*)d_in[1], (const float*)d_in[3],
        (const float*)d_in[5], (const float*)d_in[7]);
    qkv_mma_kernel<<<dim3(54, 4, 3), 256, GEMM_SMEM_BYTES>>>(bq, bk, bv);
    attn_mma_kernel<<<dim3(18, 16), ATT>>>();
    out_mma_kernel<<<dim3(54, 4), 256, GEMM_SMEM_BYTES>>>(bo, out);
}